// round 15
// baseline (speedup 1.0000x reference)
#include <cuda_runtime.h>
#include <math.h>
#include <stdint.h>

// ---------------------------------------------------------------------------
// Problem constants: N=32768 tokens, C=512, H=8, D=64; 64 windows x 512 tokens
// ---------------------------------------------------------------------------
// Fragment-image scratch (byte-images of mma fragment tiles):
__device__ float g_q[512 * 2 * 16384];     // attention Q (A-frag, pre-scaled)
__device__ float g_k[512 * 8 * 4096];      // attention K (B-frag)
__device__ float g_v[512 * 8 * 4096];      // attention V (PV-frag)
__device__ float g_xP[256 * 16 * 4096];    // x as GEMM A-frag images
__device__ float g_hP[256 * 16 * 4096];    // h as GEMM A-frag images
__device__ float g_wqkvP[12 * 16 * 4096];  // wqkv B-frag images
__device__ float g_woutP[4 * 16 * 4096];   // wout  B-frag images

// ---------------------------------------------------------------------------
// Helpers
// ---------------------------------------------------------------------------
__device__ __forceinline__ uint32_t cvt_tf32(float f) {
    uint32_t u; asm("cvt.rna.tf32.f32 %0, %1;" : "=r"(u) : "f"(f)); return u;
}

__device__ __forceinline__ void mma_tf32(float c[4], uint32_t a0, uint32_t a1,
                                         uint32_t a2, uint32_t a3,
                                         uint32_t b0, uint32_t b1) {
    asm volatile(
        "mma.sync.aligned.m16n8k8.row.col.f32.tf32.tf32.f32 "
        "{%0,%1,%2,%3}, {%4,%5,%6,%7}, {%8,%9}, {%0,%1,%2,%3};"
        : "+f"(c[0]), "+f"(c[1]), "+f"(c[2]), "+f"(c[3])
        : "r"(a0), "r"(a1), "r"(a2), "r"(a3), "r"(b0), "r"(b1));
}

// ---------------------------------------------------------------------------
// K0a: prepack weights into B-fragment images (R12-validated).
// ---------------------------------------------------------------------------
__global__ void prepack_b(const float* __restrict__ srcA,
                          float* __restrict__ dstA,
                          const float* __restrict__ srcB,
                          float* __restrict__ dstB)
{
    __shared__ float img[4096];
    const int z = blockIdx.z;
    if (z && blockIdx.x >= 4) return;
    const int jdim = z ? 512 : 1536;
    const float* src = z ? srcB : srcA;
    float* dst = z ? dstB : dstA;
    const int J = blockIdx.x, s = blockIdx.y;
    const int tid = threadIdx.x;

#pragma unroll
    for (int p = 0; p < 16; p++) {
        int idx = (p << 8) + tid;       // 0..4095
        int kk = idx >> 7;              // k within chunk, 0..31
        int n  = idx & 127;             // j within tile
        float v = src[(size_t)((s << 5) + kk) * jdim + (J << 7) + n];
        int kq = kk >> 2, e = kk & 3, tk = kq >> 1;
        int base = ((((n >> 4) << 2) + tk) << 7) + ((n & 7) << 4)
                 + (kq & 1) + (((n >> 3) & 1) << 1);
        img[base + ((e ^ tk) << 2)] = __uint_as_float(cvt_tf32(v));
    }
    __syncthreads();
    float* out = dst + ((size_t)(J * 16 + s) << 12);
#pragma unroll
    for (int p = 0; p < 4; p++) {
        int i4 = (p << 8) + tid;
        *(float4*)&out[i4 << 2] = *(const float4*)&img[i4 << 2];
    }
}

// ---------------------------------------------------------------------------
// K0b: prepack x into A-fragment images (R14).
// ---------------------------------------------------------------------------
__global__ void prepack_a(const float* __restrict__ src,
                          float* __restrict__ dst)
{
    __shared__ float img[4096];
    const int M = blockIdx.x, s = blockIdx.y;
    const int tid = threadIdx.x;
#pragma unroll
    for (int p = 0; p < 4; p++) {
        int idx = (p << 8) + tid;       // float4 unit 0..1023
        int r = idx >> 3, cq = idx & 7;
        int tk = cq >> 1;
        float4 v = *(const float4*)&src[(size_t)((M << 7) + r) * 512
                                        + (s << 5) + (cq << 2)];
        int base = ((((r >> 4) << 2) + tk) << 7) + ((r & 7) << 4)
                 + ((r >> 3) & 1) + ((cq & 1) << 1);
        img[base + ((0 ^ tk) << 2)] = __uint_as_float(cvt_tf32(v.x));
        img[base + ((1 ^ tk) << 2)] = __uint_as_float(cvt_tf32(v.y));
        img[base + ((2 ^ tk) << 2)] = __uint_as_float(cvt_tf32(v.z));
        img[base + ((3 ^ tk) << 2)] = __uint_as_float(cvt_tf32(v.w));
    }
    __syncthreads();
    float* out = dst + ((size_t)(M * 16 + s) << 12);
#pragma unroll
    for (int p = 0; p < 4; p++) {
        int i4 = (p << 8) + tid;
        *(float4*)&out[i4 << 2] = *(const float4*)&img[i4 << 2];
    }
}

// ---------------------------------------------------------------------------
// tf32 mma.sync GEMM — SMEM-FREE mainloop: both operands' fragments loaded
// directly from prepacked global images via LDG.128 (L1/L2-cached; same
// offsets as the old smem reads).  No STS, no mainloop barriers.
// ---------------------------------------------------------------------------
__global__ __launch_bounds__(256, 2)
void gemm_mma(const float* __restrict__ AP, const float* __restrict__ BP,
              const float* __restrict__ bias, const int* __restrict__ coords,
              const float* __restrict__ gq, const float* __restrict__ gk,
              float* __restrict__ outp, int mode)
{
    __shared__ float sBias[128];
    __shared__ float sGam[128];
    __shared__ float sRed[128][4];

    const int tid = threadIdx.x;
    const int lane = tid & 31, wid = tid >> 5;
    const int wm = wid & 1, wn = wid >> 1;
    const int gid = lane >> 2, tig = lane & 3;
    const int m0 = blockIdx.y << 7;
    const int j0 = blockIdx.x << 7;
    const int sec = j0 >> 9;

    if (tid < 128) {
        sBias[tid] = bias[j0 + tid];
        float g = 1.0f;
        if (mode == 0) {
            if (sec == 0) g = gq[(j0 & 511) + tid];
            else if (sec == 1) g = gk[(j0 & 511) + tid];
        }
        sGam[tid] = g;
    }
    __syncthreads();   // sBias/sGam ready for epilogue

    float c[4][4][4];
#pragma unroll
    for (int mi = 0; mi < 4; mi++)
#pragma unroll
        for (int ni = 0; ni < 4; ni++)
#pragma unroll
            for (int q = 0; q < 4; q++) c[mi][ni][q] = 0.f;

    const float* aBase = AP + ((size_t)blockIdx.y << 16);
    const float* bBase = BP + ((size_t)blockIdx.x << 16);

    for (int s = 0; s < 16; s++) {
        const float* asrc = aBase + ((size_t)s << 12);
        const float* bsrc = bBase + ((size_t)s << 12);
#pragma unroll
        for (int tk = 0; tk < 4; tk++) {
            const int lx = ((lane ^ tk) << 2);
            uint4 a[4];
#pragma unroll
            for (int mi = 0; mi < 4; mi++)
                a[mi] = *(const uint4*)&asrc[(((((wm << 2) + mi) << 2) + tk) << 7) + lx];
            uint4 b[2];
#pragma unroll
            for (int pi = 0; pi < 2; pi++)
                b[pi] = *(const uint4*)&bsrc[(((((wn << 1) + pi) << 2) + tk) << 7) + lx];
#pragma unroll
            for (int mi = 0; mi < 4; mi++)
#pragma unroll
                for (int pi = 0; pi < 2; pi++) {
                    mma_tf32(c[mi][pi * 2],     a[mi].x, a[mi].y, a[mi].z, a[mi].w,
                             b[pi].x, b[pi].y);
                    mma_tf32(c[mi][pi * 2 + 1], a[mi].x, a[mi].y, a[mi].z, a[mi].w,
                             b[pi].z, b[pi].w);
                }
        }
    }

    if (mode == 1) {
#pragma unroll
        for (int mi = 0; mi < 4; mi++)
#pragma unroll
            for (int ni = 0; ni < 4; ni++) {
                int col = (wn << 5) + (ni << 3) + (tig << 1);
                int rlo = m0 + (wm << 6) + (mi << 4) + gid;
                float2 v0 = make_float2(c[mi][ni][0] + sBias[col],
                                        c[mi][ni][1] + sBias[col + 1]);
                float2 v1 = make_float2(c[mi][ni][2] + sBias[col],
                                        c[mi][ni][3] + sBias[col + 1]);
                *(float2*)&outp[(size_t)rlo * 512 + j0 + col] = v0;
                *(float2*)&outp[(size_t)(rlo + 8) * 512 + j0 + col] = v1;
            }
        return;
    }

    // ---- mode 0: bias ----
#pragma unroll
    for (int mi = 0; mi < 4; mi++)
#pragma unroll
        for (int ni = 0; ni < 4; ni++) {
            int col = (wn << 5) + (ni << 3) + (tig << 1);
            c[mi][ni][0] += sBias[col];
            c[mi][ni][1] += sBias[col + 1];
            c[mi][ni][2] += sBias[col];
            c[mi][ni][3] += sBias[col + 1];
        }

    if (sec < 2) {
#pragma unroll
        for (int mi = 0; mi < 4; mi++)
#pragma unroll
            for (int h = 0; h < 2; h++) {
                float ss = 0.f;
#pragma unroll
                for (int ni = 0; ni < 4; ni++) {
                    float x0 = c[mi][ni][2 * h], x1 = c[mi][ni][2 * h + 1];
                    ss += x0 * x0 + x1 * x1;
                }
                ss += __shfl_xor_sync(0xffffffffu, ss, 1);
                ss += __shfl_xor_sync(0xffffffffu, ss, 2);
                if (tig == 0)
                    sRed[(wm << 6) + (mi << 4) + gid + (h << 3)][wn] = ss;
            }
        __syncthreads();
#pragma unroll
        for (int mi = 0; mi < 4; mi++)
#pragma unroll
            for (int h = 0; h < 2; h++) {
                int rl = (wm << 6) + (mi << 4) + gid + (h << 3);
                float tot = sRed[rl][wn] + sRed[rl][wn ^ 1];
                float inv = 8.0f / fmaxf(sqrtf(tot), 1e-12f);
#pragma unroll
                for (int ni = 0; ni < 4; ni++) {
                    int col = (wn << 5) + (ni << 3) + (tig << 1);
                    c[mi][ni][2 * h]     *= inv * sGam[col];
                    c[mi][ni][2 * h + 1] *= inv * sGam[col + 1];
                }
            }
    }

    // ---- scatter directly into attention fragment images (R13-validated) ----
    const int head = ((j0 & 511) >> 6) + (wn >> 1);
    const int dbase = ((wn & 1) << 5) + (tig << 1);

    int dpart[4][2];
#pragma unroll
    for (int ni = 0; ni < 4; ni++)
#pragma unroll
        for (int el = 0; el < 2; el++) {
            int d = dbase + (ni << 3) + el;
            int dq = d >> 2, e = d & 3;
            if (sec == 0)
                dpart[ni][el] = ((dq >> 1) << 7) + ((dq & 1) << 1) + (e << 2);
            else if (sec == 1)
                dpart[ni][el] = ((dq >> 1) << 9) + (dq & 1) + (e << 2);
            else
                dpart[ni][el] = ((dq >> 2) << 7) + (((dq >> 1) & 1) << 1)
                              + ((dq & 1) << 6) + (e << 4);
        }

#pragma unroll
    for (int mi = 0; mi < 4; mi++)
#pragma unroll
        for (int h = 0; h < 2; h++) {
            int token = m0 + (wm << 6) + (mi << 4) + gid + (h << 3);
            int cx = coords[4 * token + 1];
            int cy = coords[4 * token + 2];
            int cz = coords[4 * token + 3];
            int w = ((cx >> 3) << 4) + ((cy >> 3) << 2) + (cz >> 3);
            int m = ((cz & 7) << 6) + ((cy & 7) << 3) + (cx & 7);
            int wh_ = (w << 3) + head;

            if (sec == 0) {
                float* bp = g_q + ((size_t)((wh_ << 1) + (m >> 8)) << 14);
                int r = m & 255;
                int kp = ((r >> 4) << 10) + ((r & 7) << 4) + ((r >> 3) & 1);
#pragma unroll
                for (int ni = 0; ni < 4; ni++)
#pragma unroll
                    for (int el = 0; el < 2; el++)
                        bp[kp + dpart[ni][el]] = __uint_as_float(
                            cvt_tf32(c[mi][ni][2 * h + el] * 0.125f));
            } else if (sec == 1) {
                float* bp = g_k + ((size_t)((wh_ << 3) + (m >> 6)) << 12);
                int key = m & 63;
                int kp = ((key >> 4) << 7) + ((key & 7) << 4)
                       + (((key >> 3) & 1) << 1);
#pragma unroll
                for (int ni = 0; ni < 4; ni++)
#pragma unroll
                    for (int el = 0; el < 2; el++)
                        bp[kp + dpart[ni][el]] = __uint_as_float(
                            cvt_tf32(c[mi][ni][2 * h + el]));
            } else {
                float* bp = g_v + ((size_t)((wh_ << 3) + (m >> 6)) << 12);
                int key = m & 63;
                int kp = ((key >> 3) << 9) + ((key >> 2) & 1) + ((key & 3) << 2);
#pragma unroll
                for (int ni = 0; ni < 4; ni++)
#pragma unroll
                    for (int el = 0; el < 2; el++)
                        bp[kp + dpart[ni][el]] = __uint_as_float(
                            cvt_tf32(c[mi][ni][2 * h + el]));
            }
        }
}

// ---------------------------------------------------------------------------
// K2: window attention — sQ in smem (8-warp reuse); K/V fragments loaded
// DIRECTLY from global images via LDG.128.  No K/V staging, no buffers,
// ZERO barriers in the chunk loop.
// ---------------------------------------------------------------------------
#define ATTN_SMEM_BYTES (16384 * 4)

__global__ __launch_bounds__(256, 1)
void window_attn_mma()
{
    extern __shared__ float sm[];
    float* sQ = sm;              // 16384 floats

    const int tid = threadIdx.x;
    const int lane = tid & 31, wid = tid >> 5;
    const int gid = lane >> 2, tig = lane & 3;
    const int qt = blockIdx.x;          // 0..1
    const int wh = blockIdx.y;          // w*8 + h
    const int m0 = qt << 8;             // 256 rows per CTA

    const float* qimg = g_q + ((size_t)((wh << 1) + qt) << 14);
    const float* kimg = g_k + ((size_t)(wh << 3) << 12);
    const float* vimg = g_v + ((size_t)(wh << 3) << 12);

#pragma unroll
    for (int p = 0; p < 16; p++) {
        int i4 = (p << 8) + tid;
        *(float4*)&sQ[i4 << 2] = *(const float4*)&qimg[i4 << 2];
    }
    __syncthreads();   // sQ ready; only barrier in the kernel body

    float cO[2][8][4];
#pragma unroll
    for (int mi = 0; mi < 2; mi++)
#pragma unroll
        for (int f = 0; f < 8; f++)
#pragma unroll
            for (int q = 0; q < 4; q++) cO[mi][f][q] = 0.f;
    float mr[2][2], lr[2][2];
#pragma unroll
    for (int mi = 0; mi < 2; mi++) {
        mr[mi][0] = -1e30f; mr[mi][1] = -1e30f;
        lr[mi][0] = 0.f;    lr[mi][1] = 0.f;
    }

    for (int c = 0; c < 8; c++) {
        const float* kc = kimg + ((size_t)c << 12);
        const float* vc = vimg + ((size_t)c << 12);

        // ---- S = Q K^T : K fragments straight from global image ----
        float cS[2][8][4];
#pragma unroll
        for (int mi = 0; mi < 2; mi++)
#pragma unroll
            for (int f = 0; f < 8; f++)
#pragma unroll
                for (int q = 0; q < 4; q++) cS[mi][f][q] = 0.f;
#pragma unroll
        for (int tkd = 0; tkd < 8; tkd++) {
            uint4 qa[2];
#pragma unroll
            for (int mi = 0; mi < 2; mi++)
                qa[mi] = *(const uint4*)&sQ[(((((wid << 1) + mi) << 3) + tkd) << 7)
                                            + (lane << 2)];
#pragma unroll
            for (int tn2 = 0; tn2 < 4; tn2++) {
                uint4 kb = *(const uint4*)&kc[(((tkd << 2) + tn2) << 7) + (lane << 2)];
#pragma unroll
                for (int mi = 0; mi < 2; mi++) {
                    mma_tf32(cS[mi][tn2 * 2],     qa[mi].x, qa[mi].y, qa[mi].z,
                             qa[mi].w, kb.x, kb.y);
                    mma_tf32(cS[mi][tn2 * 2 + 1], qa[mi].x, qa[mi].y, qa[mi].z,
                             qa[mi].w, kb.z, kb.w);
                }
            }
        }

        // ---- online softmax per m-tile ----
#pragma unroll
        for (int mi = 0; mi < 2; mi++) {
            float smax0 = -1e30f, smax1 = -1e30f;
#pragma unroll
            for (int f = 0; f < 8; f++) {
                smax0 = fmaxf(smax0, fmaxf(cS[mi][f][0], cS[mi][f][1]));
                smax1 = fmaxf(smax1, fmaxf(cS[mi][f][2], cS[mi][f][3]));
            }
            smax0 = fmaxf(smax0, __shfl_xor_sync(0xffffffffu, smax0, 1));
            smax0 = fmaxf(smax0, __shfl_xor_sync(0xffffffffu, smax0, 2));
            smax1 = fmaxf(smax1, __shfl_xor_sync(0xffffffffu, smax1, 1));
            smax1 = fmaxf(smax1, __shfl_xor_sync(0xffffffffu, smax1, 2));
            float mn0 = fmaxf(mr[mi][0], smax0), mn1 = fmaxf(mr[mi][1], smax1);
            float corr0 = __expf(mr[mi][0] - mn0), corr1 = __expf(mr[mi][1] - mn1);
            mr[mi][0] = mn0; mr[mi][1] = mn1;
            float rs0 = 0.f, rs1 = 0.f;
#pragma unroll
            for (int f = 0; f < 8; f++) {
                float p0 = __expf(cS[mi][f][0] - mn0);
                float p1 = __expf(cS[mi][f][1] - mn0);
                float p2 = __expf(cS[mi][f][2] - mn1);
                float p3 = __expf(cS[mi][f][3] - mn1);
                rs0 += p0 + p1; rs1 += p2 + p3;
                cS[mi][f][0] = __uint_as_float(cvt_tf32(p0));
                cS[mi][f][1] = __uint_as_float(cvt_tf32(p1));
                cS[mi][f][2] = __uint_as_float(cvt_tf32(p2));
                cS[mi][f][3] = __uint_as_float(cvt_tf32(p3));
            }
            rs0 += __shfl_xor_sync(0xffffffffu, rs0, 1);
            rs0 += __shfl_xor_sync(0xffffffffu, rs0, 2);
            rs1 += __shfl_xor_sync(0xffffffffu, rs1, 1);
            rs1 += __shfl_xor_sync(0xffffffffu, rs1, 2);
            lr[mi][0] = lr[mi][0] * corr0 + rs0;
            lr[mi][1] = lr[mi][1] * corr1 + rs1;
#pragma unroll
            for (int f = 0; f < 8; f++) {
                cO[mi][f][0] *= corr0; cO[mi][f][1] *= corr0;
                cO[mi][f][2] *= corr1; cO[mi][f][3] *= corr1;
            }
        }

        // ---- O += P V : V fragments straight from global image ----
        const int src  = (lane & 28) | (tig >> 1);
        const int src2 = src + 2;
        const bool odd = tig & 1;
#pragma unroll
        for (int kb = 0; kb < 8; kb++) {
            uint32_t pa[2][4];
#pragma unroll
            for (int mi = 0; mi < 2; mi++) {
                float v0 = __shfl_sync(0xffffffffu, cS[mi][kb][0], src);
                float v1 = __shfl_sync(0xffffffffu, cS[mi][kb][1], src);
                float v2 = __shfl_sync(0xffffffffu, cS[mi][kb][2], src);
                float v3 = __shfl_sync(0xffffffffu, cS[mi][kb][3], src);
                float w0 = __shfl_sync(0xffffffffu, cS[mi][kb][0], src2);
                float w1 = __shfl_sync(0xffffffffu, cS[mi][kb][1], src2);
                float w2 = __shfl_sync(0xffffffffu, cS[mi][kb][2], src2);
                float w3 = __shfl_sync(0xffffffffu, cS[mi][kb][3], src2);
                pa[mi][0] = __float_as_uint(odd ? v1 : v0);
                pa[mi][1] = __float_as_uint(odd ? v3 : v2);
                pa[mi][2] = __float_as_uint(odd ? w1 : w0);
                pa[mi][3] = __float_as_uint(odd ? w3 : w2);
            }
#pragma unroll
            for (int tn = 0; tn < 4; tn++) {
                uint4 vb = *(const uint4*)&vc[(((kb << 2) + tn) << 7) + (lane << 2)];
#pragma unroll
                for (int mi = 0; mi < 2; mi++) {
                    mma_tf32(cO[mi][tn * 2],     pa[mi][0], pa[mi][1], pa[mi][2],
                             pa[mi][3], vb.x, vb.y);
                    mma_tf32(cO[mi][tn * 2 + 1], pa[mi][0], pa[mi][1], pa[mi][2],
                             pa[mi][3], vb.z, vb.w);
                }
            }
        }
    }

    // ---- epilogue: 1/l and scatter as GEMM A-frag images (R14) ----
    const int h = wh & 7;
    const int w = wh >> 3;
    const int wx = w >> 4, wy = (w >> 2) & 3, wz = w & 3;

    int jpart[8][2];
#pragma unroll
    for (int f = 0; f < 8; f++)
#pragma unroll
        for (int el = 0; el < 2; el++) {
            int kk = ((f & 3) << 3) + (tig << 1) + el;
            int cq = kk >> 2, e = kk & 3, tk = cq >> 1;
            jpart[f][el] = (tk << 7) + ((cq & 1) << 1) + ((e ^ tk) << 2);
        }

#pragma unroll
    for (int mi = 0; mi < 2; mi++)
#pragma unroll
        for (int rr = 0; rr < 2; rr++) {
            int m = m0 + (wid << 5) + (mi << 4) + gid + (rr << 3);
            int mz = m >> 6, my = (m >> 3) & 7, mx = m & 7;
            int n = (wz * 8 + mz) * 1024 + (wy * 8 + my) * 32 + (wx * 8 + mx);
            float inv = 1.0f / lr[mi][rr];
            int r = n & 127;
            int rp = ((r >> 4) << 9) + ((r & 7) << 4) + ((r >> 3) & 1);
            float* img0 = g_hP + ((size_t)(((n >> 7) << 4) + (h << 1)) << 12);
#pragma unroll
            for (int f = 0; f < 8; f++) {
                float* img = img0 + ((f >> 2) << 12);
                img[rp + jpart[f][0]] = __uint_as_float(
                    cvt_tf32(cO[mi][f][2 * rr] * inv));
                img[rp + jpart[f][1]] = __uint_as_float(
                    cvt_tf32(cO[mi][f][2 * rr + 1] * inv));
            }
        }
}

// ---------------------------------------------------------------------------
// kernel_launch
// inputs: x_feats, coords, w_qkv, b_qkv, gamma_q, gamma_k, w_out, b_out
// ---------------------------------------------------------------------------
extern "C" void kernel_launch(void* const* d_in, const int* in_sizes, int n_in,
                              void* d_out, int out_size)
{
    (void)in_sizes; (void)n_in; (void)out_size;
    const float* x      = (const float*)d_in[0];
    const int*   coords = (const int*)  d_in[1];
    const float* wqkv   = (const float*)d_in[2];
    const float* bqkv   = (const float*)d_in[3];
    const float* gq     = (const float*)d_in[4];
    const float* gk     = (const float*)d_in[5];
    const float* wout   = (const float*)d_in[6];
    const float* bout   = (const float*)d_in[7];
    float* outp = (float*)d_out;

    cudaFuncSetAttribute(window_attn_mma,
                         cudaFuncAttributeMaxDynamicSharedMemorySize,
                         ATTN_SMEM_BYTES);

    float* wqkvP;  cudaGetSymbolAddress((void**)&wqkvP, g_wqkvP);
    float* woutP;  cudaGetSymbolAddress((void**)&woutP, g_woutP);
    float* xP;     cudaGetSymbolAddress((void**)&xP,    g_xP);
    float* hP;     cudaGetSymbolAddress((void**)&hP,    g_hP);

    prepack_b<<<dim3(12, 16, 2), 256>>>(wqkv, wqkvP, wout, woutP);
    prepack_a<<<dim3(256, 16), 256>>>(x, xP);
    gemm_mma<<<dim3(12, 256), 256>>>(xP, wqkvP, bqkv, coords, gq, gk, nullptr, 0);
    window_attn_mma<<<dim3(2, 512), 256, ATTN_SMEM_BYTES>>>();
    gemm_mma<<<dim3(4, 256), 256>>>(hP, woutP, bout, nullptr, nullptr, nullptr,
                                    outp, 1);
}

// round 16
// speedup vs baseline: 1.2204x; 1.2204x over previous
#include <cuda_runtime.h>
#include <math.h>
#include <stdint.h>

// ---------------------------------------------------------------------------
// Problem constants: N=32768 tokens, C=512, H=8, D=64; 64 windows x 512 tokens
// ---------------------------------------------------------------------------
// Fragment-image scratch (byte-images of consumers' smem tiles):
__device__ float g_q[512 * 2 * 16384];     // attention Q (A-frag, pre-scaled)
__device__ float g_k[512 * 8 * 4096];      // attention K (B-frag)
__device__ float g_v[512 * 8 * 4096];      // attention V (PV-frag)
__device__ float g_hP[256 * 16 * 4096];    // h as GEMM A-frag images
__device__ float g_wqkvP[12 * 16 * 4096];  // wqkv B-frag images
__device__ float g_woutP[4 * 16 * 4096];   // wout  B-frag images

// ---------------------------------------------------------------------------
// Helpers
// ---------------------------------------------------------------------------
__device__ __forceinline__ uint32_t cvt_tf32(float f) {
    uint32_t u; asm("cvt.rna.tf32.f32 %0, %1;" : "=r"(u) : "f"(f)); return u;
}

__device__ __forceinline__ void mma_tf32(float c[4], uint32_t a0, uint32_t a1,
                                         uint32_t a2, uint32_t a3,
                                         uint32_t b0, uint32_t b1) {
    asm volatile(
        "mma.sync.aligned.m16n8k8.row.col.f32.tf32.tf32.f32 "
        "{%0,%1,%2,%3}, {%4,%5,%6,%7}, {%8,%9}, {%0,%1,%2,%3};"
        : "+f"(c[0]), "+f"(c[1]), "+f"(c[2]), "+f"(c[3])
        : "r"(a0), "r"(a1), "r"(a2), "r"(a3), "r"(b0), "r"(b1));
}

// ---------------------------------------------------------------------------
// K0: prepack weights into B-fragment images (R12-validated).
// ---------------------------------------------------------------------------
__global__ void prepack_b(const float* __restrict__ srcA,
                          float* __restrict__ dstA,
                          const float* __restrict__ srcB,
                          float* __restrict__ dstB)
{
    __shared__ float img[4096];
    const int z = blockIdx.z;
    if (z && blockIdx.x >= 4) return;
    const int jdim = z ? 512 : 1536;
    const float* src = z ? srcB : srcA;
    float* dst = z ? dstB : dstA;
    const int J = blockIdx.x, s = blockIdx.y;
    const int tid = threadIdx.x;

#pragma unroll
    for (int p = 0; p < 16; p++) {
        int idx = (p << 8) + tid;       // 0..4095
        int kk = idx >> 7;              // k within chunk, 0..31
        int n  = idx & 127;             // j within tile
        float v = src[(size_t)((s << 5) + kk) * jdim + (J << 7) + n];
        int kq = kk >> 2, e = kk & 3, tk = kq >> 1;
        int base = ((((n >> 4) << 2) + tk) << 7) + ((n & 7) << 4)
                 + (kq & 1) + (((n >> 3) & 1) << 1);
        img[base + ((e ^ tk) << 2)] = __uint_as_float(cvt_tf32(v));
    }
    __syncthreads();
    float* out = dst + ((size_t)(J * 16 + s) << 12);
#pragma unroll
    for (int p = 0; p < 4; p++) {
        int i4 = (p << 8) + tid;
        *(float4*)&out[i4 << 2] = *(const float4*)&img[i4 << 2];
    }
}

// ---------------------------------------------------------------------------
// tf32 mma.sync GEMM (R13-validated core): C[128,128] tile, K=512, chunk 32,
// static smem, 2 CTAs/SM.  B always copied from prepacked images.
// mode 0: A staged from raw x (cvt+frag); epilogue -> q/k/v images.
// mode 1: A copied from g_hP images; epilogue -> output.
// ---------------------------------------------------------------------------
__global__ __launch_bounds__(256, 2)
void gemm_mma(const float* __restrict__ A, const float* __restrict__ BP,
              const float* __restrict__ bias, const int* __restrict__ coords,
              const float* __restrict__ gq, const float* __restrict__ gk,
              float* __restrict__ outp, int mode)
{
    __shared__ float sA[4096];
    __shared__ float sB[4096];
    __shared__ float sBias[128];
    __shared__ float sGam[128];
    __shared__ float sRed[128][4];

    const int tid = threadIdx.x;
    const int lane = tid & 31, wid = tid >> 5;
    const int wm = wid & 1, wn = wid >> 1;
    const int gid = lane >> 2, tig = lane & 3;
    const int m0 = blockIdx.y << 7;
    const int j0 = blockIdx.x << 7;
    const int sec = j0 >> 9;

    if (tid < 128) {
        sBias[tid] = bias[j0 + tid];
        float g = 1.0f;
        if (mode == 0) {
            if (sec == 0) g = gq[(j0 & 511) + tid];
            else if (sec == 1) g = gk[(j0 & 511) + tid];
        }
        sGam[tid] = g;
    }

    float c[4][4][4];
#pragma unroll
    for (int mi = 0; mi < 4; mi++)
#pragma unroll
        for (int ni = 0; ni < 4; ni++)
#pragma unroll
            for (int q = 0; q < 4; q++) c[mi][ni][q] = 0.f;

    const float* bBase = BP + ((size_t)blockIdx.x << 16);
    const float* aImg  = A + ((size_t)blockIdx.y << 16);   // mode 1 only

    for (int s = 0; s < 16; s++) {
        if (s) __syncthreads();
        if (mode == 0) {
            const int kb = s << 5;
#pragma unroll
            for (int p = 0; p < 4; p++) {
                int idx = (p << 8) + tid;
                int r = idx >> 3, cq = idx & 7;
                int tk = cq >> 1;
                float4 v = *(const float4*)&A[(size_t)(m0 + r) * 512 + kb + (cq << 2)];
                int base = ((((r >> 4) << 2) + tk) << 7) + ((r & 7) << 4)
                         + ((r >> 3) & 1) + ((cq & 1) << 1);
                sA[base + ((0 ^ tk) << 2)] = __uint_as_float(cvt_tf32(v.x));
                sA[base + ((1 ^ tk) << 2)] = __uint_as_float(cvt_tf32(v.y));
                sA[base + ((2 ^ tk) << 2)] = __uint_as_float(cvt_tf32(v.z));
                sA[base + ((3 ^ tk) << 2)] = __uint_as_float(cvt_tf32(v.w));
            }
        } else {
            const float* asrc = aImg + ((size_t)s << 12);
#pragma unroll
            for (int p = 0; p < 4; p++) {
                int i4 = (p << 8) + tid;
                *(float4*)&sA[i4 << 2] = *(const float4*)&asrc[i4 << 2];
            }
        }
        {
            const float* bsrc = bBase + ((size_t)s << 12);
#pragma unroll
            for (int p = 0; p < 4; p++) {
                int i4 = (p << 8) + tid;
                *(float4*)&sB[i4 << 2] = *(const float4*)&bsrc[i4 << 2];
            }
        }
        __syncthreads();
#pragma unroll
        for (int tk = 0; tk < 4; tk++) {
            const int lx = ((lane ^ tk) << 2);
            uint4 a[4];
#pragma unroll
            for (int mi = 0; mi < 4; mi++)
                a[mi] = *(const uint4*)&sA[(((((wm << 2) + mi) << 2) + tk) << 7) + lx];
            uint4 b[2];
#pragma unroll
            for (int pi = 0; pi < 2; pi++)
                b[pi] = *(const uint4*)&sB[(((((wn << 1) + pi) << 2) + tk) << 7) + lx];
#pragma unroll
            for (int mi = 0; mi < 4; mi++)
#pragma unroll
                for (int pi = 0; pi < 2; pi++) {
                    mma_tf32(c[mi][pi * 2],     a[mi].x, a[mi].y, a[mi].z, a[mi].w,
                             b[pi].x, b[pi].y);
                    mma_tf32(c[mi][pi * 2 + 1], a[mi].x, a[mi].y, a[mi].z, a[mi].w,
                             b[pi].z, b[pi].w);
                }
        }
    }

    if (mode == 1) {
#pragma unroll
        for (int mi = 0; mi < 4; mi++)
#pragma unroll
            for (int ni = 0; ni < 4; ni++) {
                int col = (wn << 5) + (ni << 3) + (tig << 1);
                int rlo = m0 + (wm << 6) + (mi << 4) + gid;
                float2 v0 = make_float2(c[mi][ni][0] + sBias[col],
                                        c[mi][ni][1] + sBias[col + 1]);
                float2 v1 = make_float2(c[mi][ni][2] + sBias[col],
                                        c[mi][ni][3] + sBias[col + 1]);
                *(float2*)&outp[(size_t)rlo * 512 + j0 + col] = v0;
                *(float2*)&outp[(size_t)(rlo + 8) * 512 + j0 + col] = v1;
            }
        return;
    }

    // ---- mode 0: bias ----
#pragma unroll
    for (int mi = 0; mi < 4; mi++)
#pragma unroll
        for (int ni = 0; ni < 4; ni++) {
            int col = (wn << 5) + (ni << 3) + (tig << 1);
            c[mi][ni][0] += sBias[col];
            c[mi][ni][1] += sBias[col + 1];
            c[mi][ni][2] += sBias[col];
            c[mi][ni][3] += sBias[col + 1];
        }

    if (sec < 2) {
#pragma unroll
        for (int mi = 0; mi < 4; mi++)
#pragma unroll
            for (int h = 0; h < 2; h++) {
                float ss = 0.f;
#pragma unroll
                for (int ni = 0; ni < 4; ni++) {
                    float x0 = c[mi][ni][2 * h], x1 = c[mi][ni][2 * h + 1];
                    ss += x0 * x0 + x1 * x1;
                }
                ss += __shfl_xor_sync(0xffffffffu, ss, 1);
                ss += __shfl_xor_sync(0xffffffffu, ss, 2);
                if (tig == 0)
                    sRed[(wm << 6) + (mi << 4) + gid + (h << 3)][wn] = ss;
            }
        __syncthreads();
#pragma unroll
        for (int mi = 0; mi < 4; mi++)
#pragma unroll
            for (int h = 0; h < 2; h++) {
                int rl = (wm << 6) + (mi << 4) + gid + (h << 3);
                float tot = sRed[rl][wn] + sRed[rl][wn ^ 1];
                float inv = 8.0f / fmaxf(sqrtf(tot), 1e-12f);
#pragma unroll
                for (int ni = 0; ni < 4; ni++) {
                    int col = (wn << 5) + (ni << 3) + (tig << 1);
                    c[mi][ni][2 * h]     *= inv * sGam[col];
                    c[mi][ni][2 * h + 1] *= inv * sGam[col + 1];
                }
            }
    }

    // ---- scatter into attention fragment images (R13-validated) ----
    const int head = ((j0 & 511) >> 6) + (wn >> 1);
    const int dbase = ((wn & 1) << 5) + (tig << 1);

    int dpart[4][2];
#pragma unroll
    for (int ni = 0; ni < 4; ni++)
#pragma unroll
        for (int el = 0; el < 2; el++) {
            int d = dbase + (ni << 3) + el;
            int dq = d >> 2, e = d & 3;
            if (sec == 0)
                dpart[ni][el] = ((dq >> 1) << 7) + ((dq & 1) << 1) + (e << 2);
            else if (sec == 1)
                dpart[ni][el] = ((dq >> 1) << 9) + (dq & 1) + (e << 2);
            else
                dpart[ni][el] = ((dq >> 2) << 7) + (((dq >> 1) & 1) << 1)
                              + ((dq & 1) << 6) + (e << 4);
        }

#pragma unroll
    for (int mi = 0; mi < 4; mi++)
#pragma unroll
        for (int h = 0; h < 2; h++) {
            int token = m0 + (wm << 6) + (mi << 4) + gid + (h << 3);
            int cx = coords[4 * token + 1];
            int cy = coords[4 * token + 2];
            int cz = coords[4 * token + 3];
            int w = ((cx >> 3) << 4) + ((cy >> 3) << 2) + (cz >> 3);
            int m = ((cz & 7) << 6) + ((cy & 7) << 3) + (cx & 7);
            int wh_ = (w << 3) + head;

            if (sec == 0) {
                float* bp = g_q + ((size_t)((wh_ << 1) + (m >> 8)) << 14);
                int r = m & 255;
                int kp = ((r >> 4) << 10) + ((r & 7) << 4) + ((r >> 3) & 1);
#pragma unroll
                for (int ni = 0; ni < 4; ni++)
#pragma unroll
                    for (int el = 0; el < 2; el++)
                        bp[kp + dpart[ni][el]] = __uint_as_float(
                            cvt_tf32(c[mi][ni][2 * h + el] * 0.125f));
            } else if (sec == 1) {
                float* bp = g_k + ((size_t)((wh_ << 3) + (m >> 6)) << 12);
                int key = m & 63;
                int kp = ((key >> 4) << 7) + ((key & 7) << 4)
                       + (((key >> 3) & 1) << 1);
#pragma unroll
                for (int ni = 0; ni < 4; ni++)
#pragma unroll
                    for (int el = 0; el < 2; el++)
                        bp[kp + dpart[ni][el]] = __uint_as_float(
                            cvt_tf32(c[mi][ni][2 * h + el]));
            } else {
                float* bp = g_v + ((size_t)((wh_ << 3) + (m >> 6)) << 12);
                int key = m & 63;
                int kp = ((key >> 3) << 9) + ((key >> 2) & 1) + ((key & 3) << 2);
#pragma unroll
                for (int ni = 0; ni < 4; ni++)
#pragma unroll
                    for (int el = 0; el < 2; el++)
                        bp[kp + dpart[ni][el]] = __uint_as_float(
                            cvt_tf32(c[mi][ni][2 * h + el]));
            }
        }
}

// ---------------------------------------------------------------------------
// K2: window attention — smem image-copy staging, triple buffer, one barrier
// per chunk (R8/R13-validated).  Epilogue writes h as GEMM A-frag images.
// ---------------------------------------------------------------------------
#define ATTN_SMEM_BYTES ((8192 * 2 + 3 * 4096 + 3 * 4096) * 4)

__global__ __launch_bounds__(256, 1)
void window_attn_mma()
{
    extern __shared__ float sm[];
    float* sQ = sm;              // 16384 floats
    float* sK = sm + 16384;      // 3 x 4096 floats
    float* sV = sm + 16384 + 3 * 4096;   // 3 x 4096 floats

    const int tid = threadIdx.x;
    const int lane = tid & 31, wid = tid >> 5;
    const int gid = lane >> 2, tig = lane & 3;
    const int qt = blockIdx.x;          // 0..1
    const int wh = blockIdx.y;          // w*8 + h
    const int m0 = qt << 8;             // 256 rows per CTA

    const float* qimg = g_q + ((size_t)((wh << 1) + qt) << 14);
    const float* kimg = g_k + ((size_t)(wh << 3) << 12);
    const float* vimg = g_v + ((size_t)(wh << 3) << 12);

    auto stage = [&](int c, int bi) {
        float* sKc = sK + bi * 4096;
        float* sVc = sV + bi * 4096;
        const float* ks = kimg + ((size_t)c << 12);
        const float* vs = vimg + ((size_t)c << 12);
#pragma unroll
        for (int p = 0; p < 4; p++) {
            int i4 = (p << 8) + tid;
            *(float4*)&sKc[i4 << 2] = *(const float4*)&ks[i4 << 2];
            *(float4*)&sVc[i4 << 2] = *(const float4*)&vs[i4 << 2];
        }
    };

#pragma unroll
    for (int p = 0; p < 16; p++) {
        int i4 = (p << 8) + tid;
        *(float4*)&sQ[i4 << 2] = *(const float4*)&qimg[i4 << 2];
    }
    stage(0, 0);

    float cO[2][8][4];
#pragma unroll
    for (int mi = 0; mi < 2; mi++)
#pragma unroll
        for (int f = 0; f < 8; f++)
#pragma unroll
            for (int q = 0; q < 4; q++) cO[mi][f][q] = 0.f;
    float mr[2][2], lr[2][2];
#pragma unroll
    for (int mi = 0; mi < 2; mi++) {
        mr[mi][0] = -1e30f; mr[mi][1] = -1e30f;
        lr[mi][0] = 0.f;    lr[mi][1] = 0.f;
    }

    int bufc = 0;
    for (int c = 0; c < 8; c++) {
        if (c < 7) {
            int bn = bufc + 1; if (bn == 3) bn = 0;
            stage(c + 1, bn);
        }
        __syncthreads();
        const float* sKc = sK + bufc * 4096;
        const float* sVc = sV + bufc * 4096;

        float cS[2][8][4];
#pragma unroll
        for (int mi = 0; mi < 2; mi++)
#pragma unroll
            for (int f = 0; f < 8; f++)
#pragma unroll
                for (int q = 0; q < 4; q++) cS[mi][f][q] = 0.f;
#pragma unroll
        for (int tkd = 0; tkd < 8; tkd++) {
            uint4 qa[2];
#pragma unroll
            for (int mi = 0; mi < 2; mi++)
                qa[mi] = *(const uint4*)&sQ[(((((wid << 1) + mi) << 3) + tkd) << 7)
                                            + (lane << 2)];
#pragma unroll
            for (int tn2 = 0; tn2 < 4; tn2++) {
                uint4 kb = *(const uint4*)&sKc[(((tkd << 2) + tn2) << 7) + (lane << 2)];
#pragma unroll
                for (int mi = 0; mi < 2; mi++) {
                    mma_tf32(cS[mi][tn2 * 2],     qa[mi].x, qa[mi].y, qa[mi].z,
                             qa[mi].w, kb.x, kb.y);
                    mma_tf32(cS[mi][tn2 * 2 + 1], qa[mi].x, qa[mi].y, qa[mi].z,
                             qa[mi].w, kb.z, kb.w);
                }
            }
        }

#pragma unroll
        for (int mi = 0; mi < 2; mi++) {
            float smax0 = -1e30f, smax1 = -1e30f;
#pragma unroll
            for (int f = 0; f < 8; f++) {
                smax0 = fmaxf(smax0, fmaxf(cS[mi][f][0], cS[mi][f][1]));
                smax1 = fmaxf(smax1, fmaxf(cS[mi][f][2], cS[mi][f][3]));
            }
            smax0 = fmaxf(smax0, __shfl_xor_sync(0xffffffffu, smax0, 1));
            smax0 = fmaxf(smax0, __shfl_xor_sync(0xffffffffu, smax0, 2));
            smax1 = fmaxf(smax1, __shfl_xor_sync(0xffffffffu, smax1, 1));
            smax1 = fmaxf(smax1, __shfl_xor_sync(0xffffffffu, smax1, 2));
            float mn0 = fmaxf(mr[mi][0], smax0), mn1 = fmaxf(mr[mi][1], smax1);
            float corr0 = __expf(mr[mi][0] - mn0), corr1 = __expf(mr[mi][1] - mn1);
            mr[mi][0] = mn0; mr[mi][1] = mn1;
            float rs0 = 0.f, rs1 = 0.f;
#pragma unroll
            for (int f = 0; f < 8; f++) {
                float p0 = __expf(cS[mi][f][0] - mn0);
                float p1 = __expf(cS[mi][f][1] - mn0);
                float p2 = __expf(cS[mi][f][2] - mn1);
                float p3 = __expf(cS[mi][f][3] - mn1);
                rs0 += p0 + p1; rs1 += p2 + p3;
                cS[mi][f][0] = __uint_as_float(cvt_tf32(p0));
                cS[mi][f][1] = __uint_as_float(cvt_tf32(p1));
                cS[mi][f][2] = __uint_as_float(cvt_tf32(p2));
                cS[mi][f][3] = __uint_as_float(cvt_tf32(p3));
            }
            rs0 += __shfl_xor_sync(0xffffffffu, rs0, 1);
            rs0 += __shfl_xor_sync(0xffffffffu, rs0, 2);
            rs1 += __shfl_xor_sync(0xffffffffu, rs1, 1);
            rs1 += __shfl_xor_sync(0xffffffffu, rs1, 2);
            lr[mi][0] = lr[mi][0] * corr0 + rs0;
            lr[mi][1] = lr[mi][1] * corr1 + rs1;
#pragma unroll
            for (int f = 0; f < 8; f++) {
                cO[mi][f][0] *= corr0; cO[mi][f][1] *= corr0;
                cO[mi][f][2] *= corr1; cO[mi][f][3] *= corr1;
            }
        }

        const int src  = (lane & 28) | (tig >> 1);
        const int src2 = src + 2;
        const bool odd = tig & 1;
#pragma unroll
        for (int kb = 0; kb < 8; kb++) {
            uint32_t pa[2][4];
#pragma unroll
            for (int mi = 0; mi < 2; mi++) {
                float v0 = __shfl_sync(0xffffffffu, cS[mi][kb][0], src);
                float v1 = __shfl_sync(0xffffffffu, cS[mi][kb][1], src);
                float v2 = __shfl_sync(0xffffffffu, cS[mi][kb][2], src);
                float v3 = __shfl_sync(0xffffffffu, cS[mi][kb][3], src);
                float w0 = __shfl_sync(0xffffffffu, cS[mi][kb][0], src2);
                float w1 = __shfl_sync(0xffffffffu, cS[mi][kb][1], src2);
                float w2 = __shfl_sync(0xffffffffu, cS[mi][kb][2], src2);
                float w3 = __shfl_sync(0xffffffffu, cS[mi][kb][3], src2);
                pa[mi][0] = __float_as_uint(odd ? v1 : v0);
                pa[mi][1] = __float_as_uint(odd ? v3 : v2);
                pa[mi][2] = __float_as_uint(odd ? w1 : w0);
                pa[mi][3] = __float_as_uint(odd ? w3 : w2);
            }
#pragma unroll
            for (int tn = 0; tn < 4; tn++) {
                uint4 vb = *(const uint4*)&sVc[(((kb << 2) + tn) << 7) + (lane << 2)];
#pragma unroll
                for (int mi = 0; mi < 2; mi++) {
                    mma_tf32(cO[mi][tn * 2],     pa[mi][0], pa[mi][1], pa[mi][2],
                             pa[mi][3], vb.x, vb.y);
                    mma_tf32(cO[mi][tn * 2 + 1], pa[mi][0], pa[mi][1], pa[mi][2],
                             pa[mi][3], vb.z, vb.w);
                }
            }
        }
        bufc++; if (bufc == 3) bufc = 0;
    }

    // ---- epilogue: 1/l and scatter as GEMM A-frag images (R14 component) ----
    const int h = wh & 7;
    const int w = wh >> 3;
    const int wx = w >> 4, wy = (w >> 2) & 3, wz = w & 3;

    int jpart[8][2];
#pragma unroll
    for (int f = 0; f < 8; f++)
#pragma unroll
        for (int el = 0; el < 2; el++) {
            int kk = ((f & 3) << 3) + (tig << 1) + el;
            int cq = kk >> 2, e = kk & 3, tk = cq >> 1;
            jpart[f][el] = (tk << 7) + ((cq & 1) << 1) + ((e ^ tk) << 2);
        }

#pragma unroll
    for (int mi = 0; mi < 2; mi++)
#pragma unroll
        for (int rr = 0; rr < 2; rr++) {
            int m = m0 + (wid << 5) + (mi << 4) + gid + (rr << 3);
            int mz = m >> 6, my = (m >> 3) & 7, mx = m & 7;
            int n = (wz * 8 + mz) * 1024 + (wy * 8 + my) * 32 + (wx * 8 + mx);
            float inv = 1.0f / lr[mi][rr];
            int r = n & 127;
            int rp = ((r >> 4) << 9) + ((r & 7) << 4) + ((r >> 3) & 1);
            float* img0 = g_hP + ((size_t)(((n >> 7) << 4) + (h << 1)) << 12);
#pragma unroll
            for (int f = 0; f < 8; f++) {
                float* img = img0 + ((f >> 2) << 12);
                img[rp + jpart[f][0]] = __uint_as_float(
                    cvt_tf32(cO[mi][f][2 * rr] * inv));
                img[rp + jpart[f][1]] = __uint_as_float(
                    cvt_tf32(cO[mi][f][2 * rr + 1] * inv));
            }
        }
}

// ---------------------------------------------------------------------------
// kernel_launch
// inputs: x_feats, coords, w_qkv, b_qkv, gamma_q, gamma_k, w_out, b_out
// ---------------------------------------------------------------------------
extern "C" void kernel_launch(void* const* d_in, const int* in_sizes, int n_in,
                              void* d_out, int out_size)
{
    (void)in_sizes; (void)n_in; (void)out_size;
    const float* x      = (const float*)d_in[0];
    const int*   coords = (const int*)  d_in[1];
    const float* wqkv   = (const float*)d_in[2];
    const float* bqkv   = (const float*)d_in[3];
    const float* gq     = (const float*)d_in[4];
    const float* gk     = (const float*)d_in[5];
    const float* wout   = (const float*)d_in[6];
    const float* bout   = (const float*)d_in[7];
    float* outp = (float*)d_out;

    cudaFuncSetAttribute(window_attn_mma,
                         cudaFuncAttributeMaxDynamicSharedMemorySize,
                         ATTN_SMEM_BYTES);

    float* wqkvP;  cudaGetSymbolAddress((void**)&wqkvP, g_wqkvP);
    float* woutP;  cudaGetSymbolAddress((void**)&woutP, g_woutP);
    float* hP;     cudaGetSymbolAddress((void**)&hP,    g_hP);

    prepack_b<<<dim3(12, 16, 2), 256>>>(wqkv, wqkvP, wout, woutP);
    gemm_mma<<<dim3(12, 256), 256>>>(x, wqkvP, bqkv, coords, gq, gk, nullptr, 0);
    window_attn_mma<<<dim3(2, 512), 256, ATTN_SMEM_BYTES>>>();
    gemm_mma<<<dim3(4, 256), 256>>>(hP, woutP, bout, nullptr, nullptr, nullptr,
                                    outp, 1);
}

// round 17
// speedup vs baseline: 1.2922x; 1.0588x over previous
#include <cuda_runtime.h>
#include <math.h>
#include <stdint.h>

// ---------------------------------------------------------------------------
// Problem constants: N=32768 tokens, C=512, H=8, D=64; 64 windows x 512 tokens
// ---------------------------------------------------------------------------
// g_q: per (wh, qt<2) a 16384-float A-frag image (Q pre-scaled+cvt'd)
// g_k: per (wh, chunk<8) a 4096-float B-frag image (cvt'd)
// g_v: per (wh, chunk<8) a 4096-float PV-frag image (cvt'd)
__device__ float g_q[512 * 2 * 16384];
__device__ float g_k[512 * 8 * 4096];
__device__ float g_v[512 * 8 * 4096];
__device__ float g_h[32768 * 512];         // [n][h*64+d] (inverse-permuted)
__device__ float g_wqkvP[12 * 16 * 4096];  // wqkv prepacked B-frag images
__device__ float g_woutP[4 * 16 * 4096];   // wout  prepacked B-frag images

// ---------------------------------------------------------------------------
// Helpers
// ---------------------------------------------------------------------------
__device__ __forceinline__ uint32_t cvt_tf32(float f) {
    uint32_t u; asm("cvt.rna.tf32.f32 %0, %1;" : "=r"(u) : "f"(f)); return u;
}

__device__ __forceinline__ void mma_tf32(float c[4], uint32_t a0, uint32_t a1,
                                         uint32_t a2, uint32_t a3,
                                         uint32_t b0, uint32_t b1) {
    asm volatile(
        "mma.sync.aligned.m16n8k8.row.col.f32.tf32.tf32.f32 "
        "{%0,%1,%2,%3}, {%4,%5,%6,%7}, {%8,%9}, {%0,%1,%2,%3};"
        : "+f"(c[0]), "+f"(c[1]), "+f"(c[2]), "+f"(c[3])
        : "r"(a0), "r"(a1), "r"(a2), "r"(a3), "r"(b0), "r"(b1));
}

// ---------------------------------------------------------------------------
// K0: prepack weights into B-fragment smem images (R12-validated).
// ---------------------------------------------------------------------------
__global__ void prepack_b(const float* __restrict__ srcA,
                          float* __restrict__ dstA,
                          const float* __restrict__ srcB,
                          float* __restrict__ dstB)
{
    __shared__ float img[4096];
    const int z = blockIdx.z;
    if (z && blockIdx.x >= 4) return;
    const int jdim = z ? 512 : 1536;
    const float* src = z ? srcB : srcA;
    float* dst = z ? dstB : dstA;
    const int J = blockIdx.x, s = blockIdx.y;
    const int tid = threadIdx.x;

#pragma unroll
    for (int p = 0; p < 16; p++) {
        int idx = (p << 8) + tid;       // 0..4095
        int kk = idx >> 7;              // k within chunk, 0..31
        int n  = idx & 127;             // j within tile
        float v = src[(size_t)((s << 5) + kk) * jdim + (J << 7) + n];
        int kq = kk >> 2, e = kk & 3, tk = kq >> 1;
        int base = ((((n >> 4) << 2) + tk) << 7) + ((n & 7) << 4)
                 + (kq & 1) + (((n >> 3) & 1) << 1);
        img[base + ((e ^ tk) << 2)] = __uint_as_float(cvt_tf32(v));
    }
    __syncthreads();
    float* out = dst + ((size_t)(J * 16 + s) << 12);
#pragma unroll
    for (int p = 0; p < 4; p++) {
        int i4 = (p << 8) + tid;        // float4 unit 0..1023
        *(float4*)&out[i4 << 2] = *(const float4*)&img[i4 << 2];
    }
}

// ---------------------------------------------------------------------------
// tf32 mma.sync GEMM (R6/R12-validated): C[128,128] tile, K=512, chunk 32,
// static smem, 2 CTAs/SM, B streamed from prepacked fragment images.
// mode 0 epilogue writes q/k/v DIRECTLY as attention fragment images
// (same values as before: identical fp32 in, identical cvt order).
// ---------------------------------------------------------------------------
__global__ __launch_bounds__(256, 2)
void gemm_mma(const float* __restrict__ A, const float* __restrict__ BP,
              const float* __restrict__ bias, const int* __restrict__ coords,
              const float* __restrict__ gq, const float* __restrict__ gk,
              float* __restrict__ outp, int mode)
{
    __shared__ float sA[4096];
    __shared__ float sB[4096];
    __shared__ float sBias[128];
    __shared__ float sGam[128];
    __shared__ float sRed[128][4];

    const int tid = threadIdx.x;
    const int lane = tid & 31, wid = tid >> 5;
    const int wm = wid & 1, wn = wid >> 1;
    const int gid = lane >> 2, tig = lane & 3;
    const int m0 = blockIdx.y << 7;
    const int j0 = blockIdx.x << 7;
    const int sec = j0 >> 9;

    if (tid < 128) {
        sBias[tid] = bias[j0 + tid];
        float g = 1.0f;
        if (mode == 0) {
            if (sec == 0) g = gq[(j0 & 511) + tid];
            else if (sec == 1) g = gk[(j0 & 511) + tid];
        }
        sGam[tid] = g;
    }

    float c[4][4][4];
#pragma unroll
    for (int mi = 0; mi < 4; mi++)
#pragma unroll
        for (int ni = 0; ni < 4; ni++)
#pragma unroll
            for (int q = 0; q < 4; q++) c[mi][ni][q] = 0.f;

    const float* bBase = BP + ((size_t)blockIdx.x << 16);

    for (int s = 0; s < 16; s++) {
        const int kb = s << 5;
        if (s) __syncthreads();
#pragma unroll
        for (int p = 0; p < 4; p++) {
            int idx = (p << 8) + tid;
            int r = idx >> 3, cq = idx & 7;
            int tk = cq >> 1;
            float4 v = *(const float4*)&A[(size_t)(m0 + r) * 512 + kb + (cq << 2)];
            int base = ((((r >> 4) << 2) + tk) << 7) + ((r & 7) << 4)
                     + ((r >> 3) & 1) + ((cq & 1) << 1);
            sA[base + ((0 ^ tk) << 2)] = __uint_as_float(cvt_tf32(v.x));
            sA[base + ((1 ^ tk) << 2)] = __uint_as_float(cvt_tf32(v.y));
            sA[base + ((2 ^ tk) << 2)] = __uint_as_float(cvt_tf32(v.z));
            sA[base + ((3 ^ tk) << 2)] = __uint_as_float(cvt_tf32(v.w));
        }
        {
            const float* bsrc = bBase + ((size_t)s << 12);
#pragma unroll
            for (int p = 0; p < 4; p++) {
                int i4 = (p << 8) + tid;
                *(float4*)&sB[i4 << 2] = *(const float4*)&bsrc[i4 << 2];
            }
        }
        __syncthreads();
#pragma unroll
        for (int tk = 0; tk < 4; tk++) {
            const int lx = ((lane ^ tk) << 2);
            uint4 a[4];
#pragma unroll
            for (int mi = 0; mi < 4; mi++)
                a[mi] = *(const uint4*)&sA[(((((wm << 2) + mi) << 2) + tk) << 7) + lx];
            uint4 b[2];
#pragma unroll
            for (int pi = 0; pi < 2; pi++)
                b[pi] = *(const uint4*)&sB[(((((wn << 1) + pi) << 2) + tk) << 7) + lx];
#pragma unroll
            for (int mi = 0; mi < 4; mi++)
#pragma unroll
                for (int pi = 0; pi < 2; pi++) {
                    mma_tf32(c[mi][pi * 2],     a[mi].x, a[mi].y, a[mi].z, a[mi].w,
                             b[pi].x, b[pi].y);
                    mma_tf32(c[mi][pi * 2 + 1], a[mi].x, a[mi].y, a[mi].z, a[mi].w,
                             b[pi].z, b[pi].w);
                }
        }
    }

    if (mode == 1) {
#pragma unroll
        for (int mi = 0; mi < 4; mi++)
#pragma unroll
            for (int ni = 0; ni < 4; ni++) {
                int col = (wn << 5) + (ni << 3) + (tig << 1);
                int rlo = m0 + (wm << 6) + (mi << 4) + gid;
                float2 v0 = make_float2(c[mi][ni][0] + sBias[col],
                                        c[mi][ni][1] + sBias[col + 1]);
                float2 v1 = make_float2(c[mi][ni][2] + sBias[col],
                                        c[mi][ni][3] + sBias[col + 1]);
                *(float2*)&outp[(size_t)rlo * 512 + j0 + col] = v0;
                *(float2*)&outp[(size_t)(rlo + 8) * 512 + j0 + col] = v1;
            }
        return;
    }

    // ---- mode 0: bias ----
#pragma unroll
    for (int mi = 0; mi < 4; mi++)
#pragma unroll
        for (int ni = 0; ni < 4; ni++) {
            int col = (wn << 5) + (ni << 3) + (tig << 1);
            c[mi][ni][0] += sBias[col];
            c[mi][ni][1] += sBias[col + 1];
            c[mi][ni][2] += sBias[col];
            c[mi][ni][3] += sBias[col + 1];
        }

    if (sec < 2) {
#pragma unroll
        for (int mi = 0; mi < 4; mi++)
#pragma unroll
            for (int h = 0; h < 2; h++) {
                float ss = 0.f;
#pragma unroll
                for (int ni = 0; ni < 4; ni++) {
                    float x0 = c[mi][ni][2 * h], x1 = c[mi][ni][2 * h + 1];
                    ss += x0 * x0 + x1 * x1;
                }
                ss += __shfl_xor_sync(0xffffffffu, ss, 1);
                ss += __shfl_xor_sync(0xffffffffu, ss, 2);
                if (tig == 0)
                    sRed[(wm << 6) + (mi << 4) + gid + (h << 3)][wn] = ss;
            }
        __syncthreads();
#pragma unroll
        for (int mi = 0; mi < 4; mi++)
#pragma unroll
            for (int h = 0; h < 2; h++) {
                int rl = (wm << 6) + (mi << 4) + gid + (h << 3);
                float tot = sRed[rl][wn] + sRed[rl][wn ^ 1];
                float inv = 8.0f / fmaxf(sqrtf(tot), 1e-12f);
#pragma unroll
                for (int ni = 0; ni < 4; ni++) {
                    int col = (wn << 5) + (ni << 3) + (tig << 1);
                    c[mi][ni][2 * h]     *= inv * sGam[col];
                    c[mi][ni][2 * h + 1] *= inv * sGam[col + 1];
                }
            }
    }

    // ---- scatter directly into attention fragment images ----
    const int head = ((j0 & 511) >> 6) + (wn >> 1);
    const int dbase = ((wn & 1) << 5) + (tig << 1);

    // d-dependent index parts (separable; verified against attention staging)
    int dpart[4][2];
#pragma unroll
    for (int ni = 0; ni < 4; ni++)
#pragma unroll
        for (int el = 0; el < 2; el++) {
            int d = dbase + (ni << 3) + el;
            int dq = d >> 2, e = d & 3;
            if (sec == 0)
                dpart[ni][el] = ((dq >> 1) << 7) + ((dq & 1) << 1) + (e << 2);
            else if (sec == 1)
                dpart[ni][el] = ((dq >> 1) << 9) + (dq & 1) + (e << 2);
            else
                dpart[ni][el] = ((dq >> 2) << 7) + (((dq >> 1) & 1) << 1)
                              + ((dq & 1) << 6) + (e << 4);
        }

#pragma unroll
    for (int mi = 0; mi < 4; mi++)
#pragma unroll
        for (int h = 0; h < 2; h++) {
            int token = m0 + (wm << 6) + (mi << 4) + gid + (h << 3);
            int cx = coords[4 * token + 1];
            int cy = coords[4 * token + 2];
            int cz = coords[4 * token + 3];
            int w = ((cx >> 3) << 4) + ((cy >> 3) << 2) + (cz >> 3);
            int m = ((cz & 7) << 6) + ((cy & 7) << 3) + (cx & 7);
            int wh_ = (w << 3) + head;

            if (sec == 0) {
                float* bp = g_q + ((size_t)((wh_ << 1) + (m >> 8)) << 14);
                int r = m & 255;
                int kp = ((r >> 4) << 10) + ((r & 7) << 4) + ((r >> 3) & 1);
#pragma unroll
                for (int ni = 0; ni < 4; ni++)
#pragma unroll
                    for (int el = 0; el < 2; el++)
                        bp[kp + dpart[ni][el]] = __uint_as_float(
                            cvt_tf32(c[mi][ni][2 * h + el] * 0.125f));
            } else if (sec == 1) {
                float* bp = g_k + ((size_t)((wh_ << 3) + (m >> 6)) << 12);
                int key = m & 63;
                int kp = ((key >> 4) << 7) + ((key & 7) << 4)
                       + (((key >> 3) & 1) << 1);
#pragma unroll
                for (int ni = 0; ni < 4; ni++)
#pragma unroll
                    for (int el = 0; el < 2; el++)
                        bp[kp + dpart[ni][el]] = __uint_as_float(
                            cvt_tf32(c[mi][ni][2 * h + el]));
            } else {
                float* bp = g_v + ((size_t)((wh_ << 3) + (m >> 6)) << 12);
                int key = m & 63;
                int kp = ((key >> 3) << 9) + ((key >> 2) & 1) + ((key & 3) << 2);
#pragma unroll
                for (int ni = 0; ni < 4; ni++)
#pragma unroll
                    for (int el = 0; el < 2; el++)
                        bp[kp + dpart[ni][el]] = __uint_as_float(
                            cvt_tf32(c[mi][ni][2 * h + el]));
            }
        }
}

// ---------------------------------------------------------------------------
// K2: window attention — staging is a straight image copy (no cvt, no
// swizzle math).  Mainloop/softmax/PV unchanged from R8.  Coalesced g_h
// epilogue (float2 stores).
// ---------------------------------------------------------------------------
#define ATTN_SMEM_BYTES ((8192 * 2 + 3 * 4096 + 3 * 4096) * 4)

__global__ __launch_bounds__(256, 1)
void window_attn_mma()
{
    extern __shared__ float sm[];
    float* sQ = sm;              // 16384 floats
    float* sK = sm + 16384;      // 3 x 4096 floats
    float* sV = sm + 16384 + 3 * 4096;   // 3 x 4096 floats

    const int tid = threadIdx.x;
    const int lane = tid & 31, wid = tid >> 5;
    const int gid = lane >> 2, tig = lane & 3;
    const int qt = blockIdx.x;          // 0..1
    const int wh = blockIdx.y;          // w*8 + h
    const int m0 = qt << 8;             // 256 rows per CTA

    const float* qimg = g_q + ((size_t)((wh << 1) + qt) << 14);
    const float* kimg = g_k + ((size_t)(wh << 3) << 12);
    const float* vimg = g_v + ((size_t)(wh << 3) << 12);

    auto stage = [&](int c, int bi) {
        float* sKc = sK + bi * 4096;
        float* sVc = sV + bi * 4096;
        const float* ks = kimg + ((size_t)c << 12);
        const float* vs = vimg + ((size_t)c << 12);
#pragma unroll
        for (int p = 0; p < 4; p++) {
            int i4 = (p << 8) + tid;
            *(float4*)&sKc[i4 << 2] = *(const float4*)&ks[i4 << 2];
            *(float4*)&sVc[i4 << 2] = *(const float4*)&vs[i4 << 2];
        }
    };

    // ---- stage Q once: straight copy ----
#pragma unroll
    for (int p = 0; p < 16; p++) {
        int i4 = (p << 8) + tid;
        *(float4*)&sQ[i4 << 2] = *(const float4*)&qimg[i4 << 2];
    }
    stage(0, 0);

    float cO[2][8][4];
#pragma unroll
    for (int mi = 0; mi < 2; mi++)
#pragma unroll
        for (int f = 0; f < 8; f++)
#pragma unroll
            for (int q = 0; q < 4; q++) cO[mi][f][q] = 0.f;
    float mr[2][2], lr[2][2];
#pragma unroll
    for (int mi = 0; mi < 2; mi++) {
        mr[mi][0] = -1e30f; mr[mi][1] = -1e30f;
        lr[mi][0] = 0.f;    lr[mi][1] = 0.f;
    }

    int bufc = 0;
    for (int c = 0; c < 8; c++) {
        if (c < 7) {
            int bn = bufc + 1; if (bn == 3) bn = 0;
            stage(c + 1, bn);
        }
        __syncthreads();
        const float* sKc = sK + bufc * 4096;
        const float* sVc = sV + bufc * 4096;

        float cS[2][8][4];
#pragma unroll
        for (int mi = 0; mi < 2; mi++)
#pragma unroll
            for (int f = 0; f < 8; f++)
#pragma unroll
                for (int q = 0; q < 4; q++) cS[mi][f][q] = 0.f;
#pragma unroll
        for (int tkd = 0; tkd < 8; tkd++) {
            uint4 qa[2];
#pragma unroll
            for (int mi = 0; mi < 2; mi++)
                qa[mi] = *(const uint4*)&sQ[(((((wid << 1) + mi) << 3) + tkd) << 7)
                                            + (lane << 2)];
#pragma unroll
            for (int tn2 = 0; tn2 < 4; tn2++) {
                uint4 kb = *(const uint4*)&sKc[(((tkd << 2) + tn2) << 7) + (lane << 2)];
#pragma unroll
                for (int mi = 0; mi < 2; mi++) {
                    mma_tf32(cS[mi][tn2 * 2],     qa[mi].x, qa[mi].y, qa[mi].z,
                             qa[mi].w, kb.x, kb.y);
                    mma_tf32(cS[mi][tn2 * 2 + 1], qa[mi].x, qa[mi].y, qa[mi].z,
                             qa[mi].w, kb.z, kb.w);
                }
            }
        }

#pragma unroll
        for (int mi = 0; mi < 2; mi++) {
            float smax0 = -1e30f, smax1 = -1e30f;
#pragma unroll
            for (int f = 0; f < 8; f++) {
                smax0 = fmaxf(smax0, fmaxf(cS[mi][f][0], cS[mi][f][1]));
                smax1 = fmaxf(smax1, fmaxf(cS[mi][f][2], cS[mi][f][3]));
            }
            smax0 = fmaxf(smax0, __shfl_xor_sync(0xffffffffu, smax0, 1));
            smax0 = fmaxf(smax0, __shfl_xor_sync(0xffffffffu, smax0, 2));
            smax1 = fmaxf(smax1, __shfl_xor_sync(0xffffffffu, smax1, 1));
            smax1 = fmaxf(smax1, __shfl_xor_sync(0xffffffffu, smax1, 2));
            float mn0 = fmaxf(mr[mi][0], smax0), mn1 = fmaxf(mr[mi][1], smax1);
            float corr0 = __expf(mr[mi][0] - mn0), corr1 = __expf(mr[mi][1] - mn1);
            mr[mi][0] = mn0; mr[mi][1] = mn1;
            float rs0 = 0.f, rs1 = 0.f;
#pragma unroll
            for (int f = 0; f < 8; f++) {
                float p0 = __expf(cS[mi][f][0] - mn0);
                float p1 = __expf(cS[mi][f][1] - mn0);
                float p2 = __expf(cS[mi][f][2] - mn1);
                float p3 = __expf(cS[mi][f][3] - mn1);
                rs0 += p0 + p1; rs1 += p2 + p3;
                cS[mi][f][0] = __uint_as_float(cvt_tf32(p0));
                cS[mi][f][1] = __uint_as_float(cvt_tf32(p1));
                cS[mi][f][2] = __uint_as_float(cvt_tf32(p2));
                cS[mi][f][3] = __uint_as_float(cvt_tf32(p3));
            }
            rs0 += __shfl_xor_sync(0xffffffffu, rs0, 1);
            rs0 += __shfl_xor_sync(0xffffffffu, rs0, 2);
            rs1 += __shfl_xor_sync(0xffffffffu, rs1, 1);
            rs1 += __shfl_xor_sync(0xffffffffu, rs1, 2);
            lr[mi][0] = lr[mi][0] * corr0 + rs0;
            lr[mi][1] = lr[mi][1] * corr1 + rs1;
#pragma unroll
            for (int f = 0; f < 8; f++) {
                cO[mi][f][0] *= corr0; cO[mi][f][1] *= corr0;
                cO[mi][f][2] *= corr1; cO[mi][f][3] *= corr1;
            }
        }

        const int src  = (lane & 28) | (tig >> 1);
        const int src2 = src + 2;
        const bool odd = tig & 1;
#pragma unroll
        for (int kb = 0; kb < 8; kb++) {
            uint32_t pa[2][4];
#pragma unroll
            for (int mi = 0; mi < 2; mi++) {
                float v0 = __shfl_sync(0xffffffffu, cS[mi][kb][0], src);
                float v1 = __shfl_sync(0xffffffffu, cS[mi][kb][1], src);
                float v2 = __shfl_sync(0xffffffffu, cS[mi][kb][2], src);
                float v3 = __shfl_sync(0xffffffffu, cS[mi][kb][3], src);
                float w0 = __shfl_sync(0xffffffffu, cS[mi][kb][0], src2);
                float w1 = __shfl_sync(0xffffffffu, cS[mi][kb][1], src2);
                float w2 = __shfl_sync(0xffffffffu, cS[mi][kb][2], src2);
                float w3 = __shfl_sync(0xffffffffu, cS[mi][kb][3], src2);
                pa[mi][0] = __float_as_uint(odd ? v1 : v0);
                pa[mi][1] = __float_as_uint(odd ? v3 : v2);
                pa[mi][2] = __float_as_uint(odd ? w1 : w0);
                pa[mi][3] = __float_as_uint(odd ? w3 : w2);
            }
#pragma unroll
            for (int tn = 0; tn < 4; tn++) {
                uint4 vb = *(const uint4*)&sVc[(((kb << 2) + tn) << 7) + (lane << 2)];
#pragma unroll
                for (int mi = 0; mi < 2; mi++) {
                    mma_tf32(cO[mi][tn * 2],     pa[mi][0], pa[mi][1], pa[mi][2],
                             pa[mi][3], vb.x, vb.y);
                    mma_tf32(cO[mi][tn * 2 + 1], pa[mi][0], pa[mi][1], pa[mi][2],
                             pa[mi][3], vb.z, vb.w);
                }
            }
        }
        bufc++; if (bufc == 3) bufc = 0;
    }

    // ---- epilogue: 1/l and coalesced inverse-permutation scatter to g_h ----
    const int w = wh >> 3, h = wh & 7;
    const int wx = w >> 4, wy = (w >> 2) & 3, wz = w & 3;
#pragma unroll
    for (int mi = 0; mi < 2; mi++)
#pragma unroll
        for (int rr = 0; rr < 2; rr++) {
            int m = m0 + (wid << 5) + (mi << 4) + gid + (rr << 3);
            int mz = m >> 6, my = (m >> 3) & 7, mx = m & 7;
            int n = (wz * 8 + mz) * 1024 + (wy * 8 + my) * 32 + (wx * 8 + mx);
            float inv = 1.0f / lr[mi][rr];
            float* dsth = g_h + (size_t)n * 512 + h * 64 + (tig << 1);
#pragma unroll
            for (int f = 0; f < 8; f++)
                *(float2*)&dsth[f << 3] =
                    make_float2(cO[mi][f][2 * rr] * inv,
                                cO[mi][f][2 * rr + 1] * inv);
        }
}

// ---------------------------------------------------------------------------
// kernel_launch
// inputs: x_feats, coords, w_qkv, b_qkv, gamma_q, gamma_k, w_out, b_out
// ---------------------------------------------------------------------------
extern "C" void kernel_launch(void* const* d_in, const int* in_sizes, int n_in,
                              void* d_out, int out_size)
{
    (void)in_sizes; (void)n_in; (void)out_size;
    const float* x      = (const float*)d_in[0];
    const int*   coords = (const int*)  d_in[1];
    const float* wqkv   = (const float*)d_in[2];
    const float* bqkv   = (const float*)d_in[3];
    const float* gq     = (const float*)d_in[4];
    const float* gk     = (const float*)d_in[5];
    const float* wout   = (const float*)d_in[6];
    const float* bout   = (const float*)d_in[7];
    float* outp = (float*)d_out;

    cudaFuncSetAttribute(window_attn_mma,
                         cudaFuncAttributeMaxDynamicSharedMemorySize,
                         ATTN_SMEM_BYTES);

    float* wqkvP;  cudaGetSymbolAddress((void**)&wqkvP, g_wqkvP);
    float* woutP;  cudaGetSymbolAddress((void**)&woutP, g_woutP);
    float* hbuf;   cudaGetSymbolAddress((void**)&hbuf,  g_h);

    prepack_b<<<dim3(12, 16, 2), 256>>>(wqkv, wqkvP, wout, woutP);
    gemm_mma<<<dim3(12, 256), 256>>>(x, wqkvP, bqkv, coords, gq, gk, nullptr, 0);
    window_attn_mma<<<dim3(2, 512), 256, ATTN_SMEM_BYTES>>>();
    gemm_mma<<<dim3(4, 256), 256>>>(hbuf, woutP, bout, nullptr, nullptr, nullptr,
                                    outp, 1);
}